// round 8
// baseline (speedup 1.0000x reference)
#include <cuda_runtime.h>
#include <cstdint>

// ---------------- problem constants ----------------
#define BATCH   32
#define HH      56
#define WW      56
#define CC      192
#define WS      7
#define SS      3
#define NHEAD   6
#define HD      32
#define NWIN    49
#define NTOK    100352
#define HID     768
#define SCALE   0.17677669529663687f

#define GM 128
#define GN 96

// weight scratch offsets (floats)
#define WOFF_QKV  0
#define WOFF_PROJ 110592
#define WOFF_FC1  147456
#define WOFF_FC2  294912
#define WTOT      442368

// ---------------- scratch ----------------
__device__ float g_xw [ (size_t)NTOK * CC  ];
__device__ float g_qkv[ (size_t)NTOK * 576 ];
__device__ float g_act[ (size_t)NTOK * HID ];
__device__ float g_wr [ WTOT ];

// ---------------- helpers ----------------
__device__ __forceinline__ uint32_t smem_u32(const void* p) {
    uint32_t a;
    asm("{ .reg .u64 t; cvta.to.shared.u64 t, %1; cvt.u32.u64 %0, t; }" : "=r"(a) : "l"(p));
    return a;
}
__device__ __forceinline__ uint32_t f2tf32(float x) {
    uint32_t u;
    asm("cvt.rna.tf32.f32 %0, %1;" : "=r"(u) : "f"(x));
    return u;
}
// windowed token index -> original token index (window reverse + roll +3,+3)
__device__ __forceinline__ size_t win2orig(int m) {
    int bb  = m / (HH * WW);
    int r   = m % (HH * WW);
    int win = r / NWIN, pq = r % NWIN;
    int wi = win >> 3, wj = win & 7;
    int p = pq / WS, q = pq % WS;
    int h = wi * WS + p + SS; if (h >= HH) h -= HH;
    int w = wj * WS + q + SS; if (w >= WW) w -= WW;
    return (size_t)bb * (HH * WW) + h * WW + w;
}

#if defined(__CUDA_ARCH_FEAT_SM103_ALL) || defined(__CUDA_ARCH_FEAT_SM100_ALL)
#define HAVE_TCGEN05 1
#else
#define HAVE_TCGEN05 0
#endif

#if HAVE_TCGEN05
__device__ __forceinline__ uint32_t elect_one() {
    uint32_t p;
    asm volatile("{\n\t.reg .pred p;\n\telect.sync _|p, 0xFFFFFFFF;\n\tselp.b32 %0, 1, 0, p;\n\t}" : "=r"(p));
    return p;
}
#define TC_ALLOC(slot, n)  asm volatile("tcgen05.alloc.cta_group::1.sync.aligned.shared::cta.b32 [%0], %1;" :: "r"(slot), "r"(n) : "memory")
#define TC_DEALLOC(t, n)   asm volatile("tcgen05.dealloc.cta_group::1.sync.aligned.b32 %0, %1;" :: "r"(t), "r"(n))
#define TC_RELINQ()        asm volatile("tcgen05.relinquish_alloc_permit.cta_group::1.sync.aligned;")
#define TC_COMMIT(mb)      asm volatile("tcgen05.commit.cta_group::1.mbarrier::arrive::one.shared::cluster.b64 [%0];" :: "r"(mb) : "memory")
#define TC_WAIT_LD()       asm volatile("tcgen05.wait::ld.sync.aligned;" ::: "memory")
#define TC_FENCE_BEFORE()  asm volatile("tcgen05.fence::before_thread_sync;" ::: "memory")
#define TC_FENCE_AFTER()   asm volatile("tcgen05.fence::after_thread_sync;" ::: "memory")
#define TC_LD_X32(r, addr) \
    asm volatile("tcgen05.ld.sync.aligned.32x32b.x32.b32 " \
        "{%0,%1,%2,%3,%4,%5,%6,%7,%8,%9,%10,%11,%12,%13,%14,%15," \
        "%16,%17,%18,%19,%20,%21,%22,%23,%24,%25,%26,%27,%28,%29,%30,%31}, [%32];" \
        : "=r"((r)[0]),"=r"((r)[1]),"=r"((r)[2]),"=r"((r)[3]),"=r"((r)[4]),"=r"((r)[5]),"=r"((r)[6]),"=r"((r)[7]), \
          "=r"((r)[8]),"=r"((r)[9]),"=r"((r)[10]),"=r"((r)[11]),"=r"((r)[12]),"=r"((r)[13]),"=r"((r)[14]),"=r"((r)[15]), \
          "=r"((r)[16]),"=r"((r)[17]),"=r"((r)[18]),"=r"((r)[19]),"=r"((r)[20]),"=r"((r)[21]),"=r"((r)[22]),"=r"((r)[23]), \
          "=r"((r)[24]),"=r"((r)[25]),"=r"((r)[26]),"=r"((r)[27]),"=r"((r)[28]),"=r"((r)[29]),"=r"((r)[30]),"=r"((r)[31]) \
        : "r"(addr))
static __device__ __forceinline__ uint64_t make_desc(uint32_t saddr) {
    uint64_t d = (uint64_t(2) << 61) | (uint64_t(1) << 46) | (uint64_t(64) << 32) | (uint64_t(1) << 16);
    return d | ((uint64_t)(saddr >> 4) & 0x3FFF);
}
__device__ __forceinline__ void mma_tf32_ss(uint32_t d, uint64_t a, uint64_t b, uint32_t idesc, bool en) {
    uint32_t e = en ? 1u : 0u;
    asm volatile(
        "{\n\t.reg .pred p;\n\tsetp.ne.u32 p, %5, 0;\n\t"
        "tcgen05.mma.cta_group::1.kind::tf32 [%0], %1, %2, %3, {%4, %4, %4, %4}, p;\n\t}"
        :: "r"(d), "l"(a), "l"(b), "r"(idesc), "r"(0u), "r"(e) : "memory");
}
#endif

#define MBAR_INIT(mb, c)   asm volatile("mbarrier.init.shared.b64 [%0], %1;" :: "r"(mb), "r"(c) : "memory")
#define MBAR_WAIT(mb, ph) do { \
    uint32_t _m = (mb), _p = (ph), _d; \
    asm volatile("{\n\t.reg .pred p;\n\tmbarrier.try_wait.parity.acquire.cta.shared::cta.b64 p, [%1], %2;\n\tselp.b32 %0, 1, 0, p;\n\t}" \
        : "=r"(_d) : "r"(_m), "r"(_p) : "memory"); \
    if (!_d) { \
        asm volatile("{\n\t.reg .pred P1;\n\tWL_%=:\n\tmbarrier.try_wait.parity.acquire.cta.shared::cta.b64 P1, [%0], %1, 0x989680;\n\t@P1 bra.uni WD_%=;\n\tbra.uni WL_%=;\n\tWD_%=:\n\t}" \
            :: "r"(_m), "r"(_p) : "memory"); \
    } } while (0)
#define FENCE_ASYNC_SMEM() asm volatile("fence.proxy.async.shared::cta;" ::: "memory")
#define CP_COMMIT() asm volatile("cp.async.commit_group;" ::: "memory")

// idesc: dtype=F32(1)<<4, atype=TF32(2)<<7, btype=TF32(2)<<10, N/8<<17, M/16<<24
#define IDESC ((1u << 4) | (2u << 7) | (2u << 10) | ((GN / 8) << 17) | ((GM / 16) << 24))

// dyn-smem: 4 stages x (A 16KB + W 12KB) + tptr + 4 mbars
#define STG      28672
#define SM_TPTR  114688
#define SM_MBAR  114696
#define SM_TOTAL 114736

// ---------------- weight pre-round prepass ----------------
__global__ __launch_bounds__(256)
void round_w_k(const float* __restrict__ qkvw, const float* __restrict__ projw,
               const float* __restrict__ fc1w, const float* __restrict__ fc2w,
               float* __restrict__ o)
{
    int i = blockIdx.x * 256 + threadIdx.x;
    float v;
    if (i < WOFF_PROJ)      v = qkvw[i];
    else if (i < WOFF_FC1)  v = projw[i - WOFF_PROJ];
    else if (i < WOFF_FC2)  v = fc1w[i - WOFF_FC1];
    else                    v = fc2w[i - WOFF_FC2];
    o[i] = __uint_as_float(f2tf32(v));
}

// ---------------- GEMM: out[m,n] = sum_k A[m,k]*W[n,k] + bias[n] ----------------
// A and W must be pre-rounded to tf32. EPI: 0 plain, 1 proj(scatter+residual),
// 2 gelu(+round), 3 residual in-place
template<int EPI>
__global__ __launch_bounds__(256, 2)
void gemm_tc(const float* __restrict__ A, const float* __restrict__ W,
             const float* __restrict__ bias, float* __restrict__ out,
             const float* __restrict__ resid, int K, int ldo)
{
    extern __shared__ char smem[];
    const int tid = threadIdx.x;
    const int warp = tid >> 5, lane = tid & 31;
    const int m0 = blockIdx.x * GM;
    const int n0 = blockIdx.y * GN;

#if HAVE_TCGEN05
    const uint32_t sb = smem_u32(smem);
    const int KC = K >> 5;

    if (warp == 0) { TC_ALLOC(sb + SM_TPTR, 128); TC_RELINQ(); }
    if (tid == 0) {
#pragma unroll
        for (int b = 0; b < 4; b++) MBAR_INIT(sb + SM_MBAR + 8 * b, 1);
    }
    __syncthreads();
    uint32_t tmem;
    asm volatile("ld.shared.b32 %0, [%1];" : "=r"(tmem) : "r"(sb + SM_TPTR));

    const float* Ab = A + (size_t)m0 * K;
    const float* Wb = W + (size_t)n0 * K;

    auto cpA = [&](int kc, int st) {
        uint32_t base = sb + st * STG;
        const float* g = Ab + kc * 32;
#pragma unroll
        for (int it = 0; it < 4; it++) {
            int f = tid + it * 256;                 // 1024 x 16B
            int row = f >> 3, c4 = f & 7;
            const float* src = g + (size_t)row * K + c4 * 4;
            uint32_t off = (row << 7) + (c4 << 4);
            off ^= (off >> 3) & 0x70;
            asm volatile("cp.async.cg.shared.global [%0], [%1], 16;"
                         :: "r"(base + off), "l"(src) : "memory");
        }
    };
    auto cpW = [&](int kc, int st) {
        uint32_t base = sb + st * STG + 16384;
        const float* g = Wb + kc * 32;
#pragma unroll
        for (int it = 0; it < 3; it++) {            // 768 x 16B
            int f = tid + it * 256;
            int row = f >> 3, c4 = f & 7;
            const float* src = g + (size_t)row * K + c4 * 4;
            uint32_t off = (row << 7) + (c4 << 4);
            off ^= (off >> 3) & 0x70;
            asm volatile("cp.async.cg.shared.global [%0], [%1], 16;"
                         :: "r"(base + off), "l"(src) : "memory");
        }
    };

    // prologue: stage chunks 0..2 (KC >= 6 for all our shapes)
    cpA(0, 0); cpW(0, 0); CP_COMMIT();
    cpA(1, 1); cpW(1, 1); CP_COMMIT();
    cpA(2, 2); cpW(2, 2); CP_COMMIT();

    for (int kc = 0; kc < KC; kc++) {
        const int st = kc & 3;
        const int lc = kc + 3;
        if (lc < KC) {
            if (kc >= 1) {                       // stage lc&3 was used by chunk kc-1
                int pk = kc - 1;
                MBAR_WAIT(sb + SM_MBAR + 8 * (pk & 3), (pk >> 2) & 1);
            }
            cpA(lc, lc & 3); cpW(lc, lc & 3);
        }
        // ALWAYS commit a group (empty in the tail) so wait_group 3 below
        // guarantees chunk kc has landed in EVERY iteration, incl. the tail.
        CP_COMMIT();
        asm volatile("cp.async.wait_group 3;" ::: "memory");   // chunk kc landed
        FENCE_ASYNC_SMEM();
        __syncthreads();
        if (warp == 0 && elect_one()) {
            uint64_t ad = make_desc(sb + st * STG);
            uint64_t bd = make_desc(sb + st * STG + 16384);
#pragma unroll
            for (int s = 0; s < 4; s++)
                mma_tf32_ss(tmem, ad + s * 2, bd + s * 2, IDESC, (kc > 0) || (s > 0));
            TC_COMMIT(sb + SM_MBAR + 8 * st);
        }
    }
    {
        int pk = KC - 1;
        MBAR_WAIT(sb + SM_MBAR + 8 * (pk & 3), (pk >> 2) & 1);
    }
    TC_FENCE_AFTER();

    if (warp < 4) {
        const int m = m0 + warp * 32 + lane;
        size_t orow = (EPI == 1) ? win2orig(m) : (size_t)m;
        float* op = out + orow * (size_t)ldo + n0;
        const float* rp = (EPI == 1 || EPI == 3) ? (resid + orow * CC + n0) : nullptr;
#pragma unroll
        for (int gblk = 0; gblk < GN / 32; gblk++) {
            uint32_t dr[32];
            TC_LD_X32(dr, tmem + gblk * 32);
            TC_WAIT_LD();
            float vv[32];
#pragma unroll
            for (int c = 0; c < 32; c++) {
                float v = __uint_as_float(dr[c]) + bias[n0 + gblk * 32 + c];
                if (EPI == 2) {
                    v = 0.5f * v * (1.0f + erff(v * 0.70710678118654752f));
                    v = __uint_as_float(f2tf32(v));   // feeds fc2 A
                }
                vv[c] = v;
            }
            if (EPI == 1 || EPI == 3) {
#pragma unroll
                for (int c4 = 0; c4 < 8; c4++) {
                    float4 rv = *(const float4*)(rp + gblk * 32 + c4 * 4);
                    float4 o = { vv[c4*4+0] + rv.x, vv[c4*4+1] + rv.y, vv[c4*4+2] + rv.z, vv[c4*4+3] + rv.w };
                    *(float4*)(op + gblk * 32 + c4 * 4) = o;
                }
            } else {
#pragma unroll
                for (int c4 = 0; c4 < 8; c4++) {
                    float4 o = { vv[c4*4+0], vv[c4*4+1], vv[c4*4+2], vv[c4*4+3] };
                    *(float4*)(op + gblk * 32 + c4 * 4) = o;
                }
            }
        }
        TC_FENCE_BEFORE();
    }
    __syncthreads();
    if (warp == 0) TC_DEALLOC(tmem, 128);

#else  // ---------- fallback: mma.sync m16n8k8 tf32 (A/W pre-rounded) ----------
    float* As = (float*)smem;                         // [128][33]
    float* Ws = (float*)(smem + 128 * 33 * 4);        // [GN][33]
    const int wm = warp >> 1, wn = warp & 1;
    const int r = lane >> 2, cq = lane & 3;
    const int NB = GN / 16;
    float acc[2][NB][4] = {};

    for (int k0 = 0; k0 < K; k0 += 32) {
#pragma unroll
        for (int it = 0; it < 16; it++) {
            int f = tid + it * 256;
            int row = f >> 5, col = f & 31;
            As[row * 33 + col] = A[(size_t)(m0 + row) * K + k0 + col];
        }
#pragma unroll
        for (int it = 0; it < GN / 8; it++) {
            int f = tid + it * 256;
            int row = f >> 5, col = f & 31;
            Ws[row * 33 + col] = W[(size_t)(n0 + row) * K + k0 + col];
        }
        __syncthreads();
#pragma unroll
        for (int kk = 0; kk < 32; kk += 8) {
            uint32_t af[2][4], bf[NB][2];
#pragma unroll
            for (int am = 0; am < 2; am++) {
                int mr = wm * 32 + am * 16;
                af[am][0] = __float_as_uint(As[(mr + r)     * 33 + kk + cq]);
                af[am][1] = __float_as_uint(As[(mr + r + 8) * 33 + kk + cq]);
                af[am][2] = __float_as_uint(As[(mr + r)     * 33 + kk + cq + 4]);
                af[am][3] = __float_as_uint(As[(mr + r + 8) * 33 + kk + cq + 4]);
            }
#pragma unroll
            for (int bn = 0; bn < NB; bn++) {
                int nc = wn * (GN / 2) + bn * 8 + r;
                bf[bn][0] = __float_as_uint(Ws[nc * 33 + kk + cq]);
                bf[bn][1] = __float_as_uint(Ws[nc * 33 + kk + cq + 4]);
            }
#pragma unroll
            for (int am = 0; am < 2; am++)
#pragma unroll
                for (int bn = 0; bn < NB; bn++)
                    asm volatile("mma.sync.aligned.m16n8k8.row.col.f32.tf32.tf32.f32 "
                        "{%0,%1,%2,%3}, {%4,%5,%6,%7}, {%8,%9}, {%0,%1,%2,%3};"
                        : "+f"(acc[am][bn][0]), "+f"(acc[am][bn][1]),
                          "+f"(acc[am][bn][2]), "+f"(acc[am][bn][3])
                        : "r"(af[am][0]), "r"(af[am][1]), "r"(af[am][2]), "r"(af[am][3]),
                          "r"(bf[bn][0]), "r"(bf[bn][1]));
        }
        __syncthreads();
    }

#pragma unroll
    for (int am = 0; am < 2; am++)
#pragma unroll
    for (int rr = 0; rr < 2; rr++) {
        int m = m0 + wm * 32 + am * 16 + r + rr * 8;
        size_t orow = (EPI == 1) ? win2orig(m) : (size_t)m;
#pragma unroll
        for (int bn = 0; bn < NB; bn++)
#pragma unroll
        for (int c2 = 0; c2 < 2; c2++) {
            int n = n0 + wn * (GN / 2) + bn * 8 + cq * 2 + c2;
            float v = acc[am][bn][rr * 2 + c2] + bias[n];
            if (EPI == 2) { v = 0.5f * v * (1.0f + erff(v * 0.70710678118654752f)); v = __uint_as_float(f2tf32(v)); }
            if (EPI == 1 || EPI == 3) v += resid[orow * CC + n];
            out[orow * (size_t)ldo + n] = v;
        }
    }
#endif
}

// ---------------- LN kernel (warp per token); output tf32-rounded ----------------
__global__ __launch_bounds__(256)
void ln_kernel(const float* __restrict__ in, const float* __restrict__ g,
               const float* __restrict__ b, float* __restrict__ outp, int gather)
{
    int warp = threadIdx.x >> 5, lane = threadIdx.x & 31;
    int m = blockIdx.x * 8 + warp;
    size_t src = gather ? win2orig(m) : (size_t)m;
    const float* xp = in + src * CC;
    float v[6];
    float sum = 0.f;
#pragma unroll
    for (int u = 0; u < 6; u++) { v[u] = xp[lane + 32 * u]; sum += v[u]; }
#pragma unroll
    for (int o = 16; o; o >>= 1) sum += __shfl_xor_sync(0xffffffffu, sum, o);
    float mu = sum * (1.0f / CC);
    float vs = 0.f;
#pragma unroll
    for (int u = 0; u < 6; u++) { float d = v[u] - mu; vs += d * d; }
#pragma unroll
    for (int o = 16; o; o >>= 1) vs += __shfl_xor_sync(0xffffffffu, vs, o);
    float rstd = rsqrtf(vs * (1.0f / CC) + 1e-5f);
    float* op = outp + (size_t)m * CC;
#pragma unroll
    for (int u = 0; u < 6; u++) {
        int c = lane + 32 * u;
        float o = (v[u] - mu) * rstd * g[c] + b[c];
        op[c] = __uint_as_float(f2tf32(o));   // feeds a GEMM A operand
    }
}

// ---------------- attention ----------------
__global__ __launch_bounds__(256)
void attn_k(const float* __restrict__ qkv, const float* __restrict__ rpb,
            float* __restrict__ outp)
{
    const int wIdx = blockIdx.x;
    const int hIdx = blockIdx.y;
    __shared__ float sq[NWIN][HD + 1];
    __shared__ float sk[NWIN][HD + 1];
    __shared__ float sv[NWIN][HD + 1];
    __shared__ float sc[NWIN][NWIN + 1];
    const int tid = threadIdx.x;
    const size_t base = (size_t)wIdx * NWIN;

    for (int idx = tid; idx < NWIN * HD; idx += 256) {
        int i = idx >> 5, d = idx & 31;
        size_t off = (base + i) * 576 + hIdx * HD + d;
        sq[i][d] = qkv[off] * SCALE;
        sk[i][d] = qkv[off + CC];
        sv[i][d] = qkv[off + 2 * CC];
    }
    __syncthreads();

    const int win = wIdx & 63;
    const int wi = win >> 3, wj = win & 7;
    for (int idx = tid; idx < NWIN * NWIN; idx += 256) {
        int i = idx / NWIN, j = idx % NWIN;
        float acc = 0.f;
#pragma unroll
        for (int d = 0; d < HD; d++) acc += sq[i][d] * sk[j][d];
        int pi = i / WS, qi = i % WS, pj = j / WS, qj = j % WS;
        int ridx = (pi - pj + WS - 1) * (2 * WS - 1) + (qi - qj + WS - 1);
        acc += rpb[ridx * NHEAD + hIdx];
        int hi = wi * WS + pi, wwi = wj * WS + qi;
        int hj = wi * WS + pj, wwj = wj * WS + qj;
        int ri = (hi < HH - WS ? 0 : (hi < HH - SS ? 1 : 2)) * 3
               + (wwi < WW - WS ? 0 : (wwi < WW - SS ? 1 : 2));
        int rj = (hj < HH - WS ? 0 : (hj < HH - SS ? 1 : 2)) * 3
               + (wwj < WW - WS ? 0 : (wwj < WW - SS ? 1 : 2));
        if (ri != rj) acc -= 100.0f;
        sc[i][j] = acc;
    }
    __syncthreads();

    if (tid < NWIN) {
        float mx = -1e30f;
#pragma unroll 7
        for (int j = 0; j < NWIN; j++) mx = fmaxf(mx, sc[tid][j]);
        float sum = 0.f;
#pragma unroll 7
        for (int j = 0; j < NWIN; j++) { float e = __expf(sc[tid][j] - mx); sc[tid][j] = e; sum += e; }
        float inv = 1.0f / sum;
#pragma unroll 7
        for (int j = 0; j < NWIN; j++) sc[tid][j] *= inv;
    }
    __syncthreads();

    for (int idx = tid; idx < NWIN * HD; idx += 256) {
        int i = idx >> 5, d = idx & 31;
        float acc = 0.f;
#pragma unroll 7
        for (int j = 0; j < NWIN; j++) acc += sc[i][j] * sv[j][d];
        outp[(base + i) * CC + hIdx * HD + d] = __uint_as_float(f2tf32(acc));  // feeds proj A
    }
}

// ---------------- launcher ----------------
extern "C" void kernel_launch(void* const* d_in, const int* in_sizes, int n_in,
                              void* d_out, int out_size)
{
    const float* x      = (const float*)d_in[0];
    const float* n1g    = (const float*)d_in[1];
    const float* n1b    = (const float*)d_in[2];
    const float* qkv_w  = (const float*)d_in[3];
    const float* qkv_b  = (const float*)d_in[4];
    const float* proj_w = (const float*)d_in[5];
    const float* proj_b = (const float*)d_in[6];
    const float* rpb    = (const float*)d_in[7];
    const float* n2g    = (const float*)d_in[8];
    const float* n2b    = (const float*)d_in[9];
    const float* fc1w   = (const float*)d_in[10];
    const float* fc1b   = (const float*)d_in[11];
    const float* fc2w   = (const float*)d_in[12];
    const float* fc2b   = (const float*)d_in[13];
    float* out = (float*)d_out;

    float *xw, *qkv, *act, *wr;
    cudaGetSymbolAddress((void**)&xw,  g_xw);
    cudaGetSymbolAddress((void**)&qkv, g_qkv);
    cudaGetSymbolAddress((void**)&act, g_act);
    cudaGetSymbolAddress((void**)&wr,  g_wr);

    cudaFuncSetAttribute(gemm_tc<0>, cudaFuncAttributeMaxDynamicSharedMemorySize, SM_TOTAL);
    cudaFuncSetAttribute(gemm_tc<1>, cudaFuncAttributeMaxDynamicSharedMemorySize, SM_TOTAL);
    cudaFuncSetAttribute(gemm_tc<2>, cudaFuncAttributeMaxDynamicSharedMemorySize, SM_TOTAL);
    cudaFuncSetAttribute(gemm_tc<3>, cudaFuncAttributeMaxDynamicSharedMemorySize, SM_TOTAL);

    // 0. pre-round weights to tf32
    round_w_k<<<WTOT / 256, 256>>>(qkv_w, proj_w, fc1w, fc2w, wr);
    // 1. LN1 + shifted-window gather (tf32-rounded out)
    ln_kernel<<<NTOK / 8, 256>>>(x, n1g, n1b, xw, 1);
    // 2. QKV: M=100352, N=576, K=192
    gemm_tc<0><<<dim3(NTOK / GM, 576 / GN), 256, SM_TOTAL>>>(xw, wr + WOFF_QKV, qkv_b, qkv, nullptr, 192, 576);
    // 3. windowed attention (writes into xw, tf32-rounded)
    attn_k<<<dim3(NTOK / NWIN, NHEAD), 256>>>(qkv, rpb, xw);
    // 4. proj + scatter + residual -> d_out
    gemm_tc<1><<<dim3(NTOK / GM, CC / GN), 256, SM_TOTAL>>>(xw, wr + WOFF_PROJ, proj_b, out, x, 192, CC);
    // 5. LN2 (reuse qkv buffer, tf32-rounded out)
    ln_kernel<<<NTOK / 8, 256>>>(out, n2g, n2b, qkv, 0);
    // 6. fc1 + GELU (tf32-rounded out): N=768
    gemm_tc<2><<<dim3(NTOK / GM, HID / GN), 256, SM_TOTAL>>>(qkv, wr + WOFF_FC1, fc1b, act, nullptr, 192, HID);
    // 7. fc2 + residual (in-place on d_out): K=768
    gemm_tc<3><<<dim3(NTOK / GM, CC / GN), 256, SM_TOTAL>>>(act, wr + WOFF_FC2, fc2b, out, out, 768, CC);
}